// round 9
// baseline (speedup 1.0000x reference)
#include <cuda_runtime.h>
#include <math.h>

#define NKNOT 1024
#define NW    1020          // NUM_KNOTS - DEGREE - 1

// fp32 images of +/-pi (np.linspace endpoints after float32 cast)
#define T_LO (-3.14159274101257324218750f)
#define T_HI ( 3.14159274101257324218750f)

// 1023/(2*pi) split hi+lo (hi = correctly-rounded fp32, lo = residual)
#define INVH_HI 162.81578063964843750f
#define INVH_LO (-8.2343605185432045e-08f)
#define S_OFF   511.5f       // pi * 1023/(2*pi), exactly representable

#define THREADS 64
#define ELEMS   4
#define TBL     1032         // 4 zero + 1020 weights + 8 zero  (258 float4 slots)

__global__ __launch_bounds__(THREADS) void bspline_act_kernel(
    const float* __restrict__ x,
    const float* __restrict__ w,
    float* __restrict__ out)
{
    // s_big[j+4] = w[j]; zeros at [0..3] and [1024..1031].
    // Tap k of interval i is w[i-3+k] = s_big[i+1+k] — always in range, no clamps.
    __shared__ float s_big[TBL];

    const int tid  = threadIdx.x;
    const int base = (blockIdx.x * THREADS + tid) * ELEMS;

    // ---- prefetch x FIRST: its latency overlaps the prologue + BAR ----
    float4 xv = *reinterpret_cast<const float4*>(x + base);

    // ---- prologue: pure copy, 4 float4 slots per thread (+2 tail), MLP=4 ----
    {
        const float4* w4 = reinterpret_cast<const float4*>(w);
        float4*       s4 = reinterpret_cast<float4*>(s_big);
        const float4  z  = make_float4(0.f, 0.f, 0.f, 0.f);

        // slot s: s4[s] = w4[s-1] for 1 <= s <= 255, else zero pad.
        float4 v[4];
#pragma unroll
        for (int q = 0; q < 4; q++) {
            int s = tid + q * THREADS;              // 0..255
            v[q] = (s >= 1) ? w4[s - 1] : z;        // s<=255 always here
        }
#pragma unroll
        for (int q = 0; q < 4; q++) {
            int s = tid + q * THREADS;
            s4[s] = v[q];
        }
        if (tid < 2) s4[256 + tid] = z;             // slots 256,257: right pad
    }
    __syncthreads();    // couples only 2 warps

    float xs[4] = {xv.x, xv.y, xv.z, xv.w};
    float r[4];

#pragma unroll
    for (int e = 0; e < 4; e++) {
        float xx = xs[e];

        // interval index
        float s1 = fmaf(xx, INVH_HI, S_OFF);
        int i = (int)s1;
        i = min(max(i, 0), NKNOT - 2);

        // compensated local coordinate: 511.5 - i exact; lo-term fixes INVH_HI's
        // representation error. u accurate to ~1e-7 vs ideal uniform grid.
        float offi = S_OFF - (float)i;
        float u = fmaf(xx, INVH_LO, fmaf(xx, INVH_HI, offi));

        // 4 unconditional weight taps (parallel LDS)
        float w0 = s_big[i + 1];
        float w1 = s_big[i + 2];
        float w2 = s_big[i + 3];
        float w3 = s_big[i + 4];

        // uniform cubic B-spline blend
        const float SIXTH = 0.16666666666666666f;
        float omu = 1.0f - u;
        float u2  = u * u;
        float u3  = u2 * u;
        float N0 = omu * omu * omu * SIXTH;
        float N1 = fmaf(3.0f, u3, fmaf(-6.0f, u2, 4.0f)) * SIXTH;
        float N2 = fmaf(-3.0f, u3, fmaf(3.0f, u2, fmaf(3.0f, u, 1.0f))) * SIXTH;
        float N3 = u3 * SIXTH;

        float acc = fmaf(N0, w0, fmaf(N1, w1, fmaf(N2, w2, N3 * w3)));
        r[e] = (xx >= T_LO && xx < T_HI) ? acc : 0.0f;
    }

    *reinterpret_cast<float4*>(out + base) = make_float4(r[0], r[1], r[2], r[3]);
}

extern "C" void kernel_launch(void* const* d_in, const int* in_sizes, int n_in,
                              void* d_out, int out_size) {
    const float* x = (const float*)d_in[0];
    const float* w = (const float*)d_in[1];
    float* out = (float*)d_out;
    int n = in_sizes[0];                         // 262144
    int blocks = n / (THREADS * ELEMS);          // 1024 CTAs -> ~7 per SM
    bspline_act_kernel<<<blocks, THREADS>>>(x, w, out);
}